// round 4
// baseline (speedup 1.0000x reference)
#include <cuda_runtime.h>
#include <math.h>
#include <stdint.h>

#define BATCH 8
#define CCH   512
#define CRD   32
#define NPIX  4096   // 64*64
#define MTILES (NPIX / 64)   // 64 m-tiles per row in scores_kernel

// ---------------- scratch (device globals; no allocations allowed) ----------
__device__ float g_Q[(size_t)BATCH * NPIX * CRD];          // [b][n][r]
__device__ float g_K[(size_t)BATCH * CRD * NPIX];          // [b][r][m]
__device__ float g_V[(size_t)BATCH * CCH * NPIX];          // [b][c][m]
__device__ float g_P[(size_t)BATCH * NPIX * NPIX];         // [b][n][m] = exp(S)
__device__ float g_O[(size_t)BATCH * CCH * NPIX];          // [b][c][n]
__device__ float g_Sp[(size_t)BATCH * NPIX * MTILES];      // partial row sums
__device__ float g_S[(size_t)BATCH * NPIX];                // row sums of exp(S)

// ---------------- kernel 1: fused Q/K projections ---------------------------
// grid (NPIX/256, BATCH), block 256, dynamic smem = 2*CRD*CCH*4 = 128KB
extern "C" __global__ void __launch_bounds__(256)
qk_kernel(const float* __restrict__ x,
          const float* __restrict__ Wq, const float* __restrict__ bq,
          const float* __restrict__ Wk, const float* __restrict__ bk)
{
    extern __shared__ float s_w[];
    float* Wqs = s_w;                 // [CRD][CCH]
    float* Wks = s_w + CRD * CCH;
    const int tid = threadIdx.x;
    for (int i = tid * 4; i < CRD * CCH; i += 256 * 4) {
        *(float4*)&Wqs[i] = *(const float4*)&Wq[i];
        *(float4*)&Wks[i] = *(const float4*)&Wk[i];
    }
    __syncthreads();

    const int b = blockIdx.y;
    const int n = blockIdx.x * 256 + tid;
    const float* xp = x + (size_t)b * CCH * NPIX + n;

    float qa[CRD], ka[CRD];
#pragma unroll
    for (int r = 0; r < CRD; r++) { qa[r] = 0.f; ka[r] = 0.f; }

    for (int c = 0; c < CCH; c += 4) {
        float x0 = xp[(size_t)(c + 0) * NPIX];
        float x1 = xp[(size_t)(c + 1) * NPIX];
        float x2 = xp[(size_t)(c + 2) * NPIX];
        float x3 = xp[(size_t)(c + 3) * NPIX];
#pragma unroll
        for (int r = 0; r < CRD; r++) {
            float4 wq = *(const float4*)&Wqs[r * CCH + c];
            qa[r] += wq.x * x0 + wq.y * x1 + wq.z * x2 + wq.w * x3;
            float4 wk = *(const float4*)&Wks[r * CCH + c];
            ka[r] += wk.x * x0 + wk.y * x1 + wk.z * x2 + wk.w * x3;
        }
    }

    float* qout = g_Q + ((size_t)b * NPIX + n) * CRD;
#pragma unroll
    for (int r = 0; r < CRD; r++) qout[r] = qa[r] + bq[r];
    float* kout = g_K + (size_t)b * CRD * NPIX + n;
#pragma unroll
    for (int r = 0; r < CRD; r++) kout[(size_t)r * NPIX] = ka[r] + bk[r];
}

// ---------------- kernel 2/6: SGEMM NN  C = A[M,K] * B[K,N] -----------------
// A row-major (k contig), B row-major (n contig). 128x128 tile, 8x8 micro.
// Double-buffered smem mainloop (one barrier per k-tile).
// epilogue: if resid: C = gamma*(acc+bias)+resid  else C = acc + (bias?bias:0)
extern "C" __global__ void __launch_bounds__(256)
sgemm_nn(const float* __restrict__ A, const float* __restrict__ B,
         float* __restrict__ C, int K, int ldn,
         size_t sB, size_t sC,
         const float* __restrict__ bias,
         const float* __restrict__ resid,
         const float* __restrict__ gamma)
{
    __shared__ float As[2][8][128];
    __shared__ float Bs[2][8][128];
    const int tid = threadIdx.x;
    const int tx = tid & 15, ty = tid >> 4;
    const int row0 = blockIdx.y * 128, col0 = blockIdx.x * 128;
    const float* Ap = A + (size_t)row0 * K;
    const float* Bp = B + (size_t)blockIdx.z * sB + col0;
    const int ar = tid >> 1, ac = (tid & 1) * 4;
    const int br = tid >> 5, bc = (tid & 31) * 4;

    float acc[8][8];
#pragma unroll
    for (int i = 0; i < 8; i++)
#pragma unroll
        for (int j = 0; j < 8; j++) acc[i][j] = 0.f;

    const int nt = K / 8;
    {
        float4 av = *(const float4*)(Ap + (size_t)ar * K + ac);
        float4 bv = *(const float4*)(Bp + (size_t)br * ldn + bc);
        As[0][ac + 0][ar] = av.x; As[0][ac + 1][ar] = av.y;
        As[0][ac + 2][ar] = av.z; As[0][ac + 3][ar] = av.w;
        *(float4*)&Bs[0][br][bc] = bv;
    }
    __syncthreads();

    for (int t = 0; t < nt; t++) {
        const int cur = t & 1, nxt = cur ^ 1;
        float4 av2, bv2;
        const bool more = (t + 1) < nt;
        if (more) {
            int kt = (t + 1) * 8;
            av2 = *(const float4*)(Ap + (size_t)ar * K + kt + ac);
            bv2 = *(const float4*)(Bp + (size_t)(kt + br) * ldn + bc);
        }
#pragma unroll
        for (int k = 0; k < 8; k++) {
            float a[8], bb[8];
            *(float4*)(a)     = *(const float4*)&As[cur][k][ty * 8];
            *(float4*)(a + 4) = *(const float4*)&As[cur][k][ty * 8 + 4];
            *(float4*)(bb)     = *(const float4*)&Bs[cur][k][tx * 8];
            *(float4*)(bb + 4) = *(const float4*)&Bs[cur][k][tx * 8 + 4];
#pragma unroll
            for (int i = 0; i < 8; i++)
#pragma unroll
                for (int j = 0; j < 8; j++) acc[i][j] += a[i] * bb[j];
        }
        if (more) {
            As[nxt][ac + 0][ar] = av2.x; As[nxt][ac + 1][ar] = av2.y;
            As[nxt][ac + 2][ar] = av2.z; As[nxt][ac + 3][ar] = av2.w;
            *(float4*)&Bs[nxt][br][bc] = bv2;
        }
        __syncthreads();
    }

    const float g = gamma ? *gamma : 0.f;
#pragma unroll
    for (int i = 0; i < 8; i++) {
        int row = row0 + ty * 8 + i;
        float bval = bias ? bias[row] : 0.f;
        size_t off = (size_t)blockIdx.z * sC + (size_t)row * ldn + col0 + tx * 8;
        float o[8];
#pragma unroll
        for (int j = 0; j < 8; j++) {
            float v = acc[i][j] + bval;
            if (resid) v = g * v + resid[off + j];
            o[j] = v;
        }
        *(float4*)&C[off]     = *(float4*)(o);
        *(float4*)&C[off + 4] = *(float4*)(o + 4);
    }
}

// ---------------- kernel 5: SGEMM NT  C[M,N] = A[M,K] * B[N,K]^T ------------
// Both A and B row-major with k contiguous. Used for out = V @ P^T.
// Double-buffered smem mainloop. Epilogue divides by per-column row-sums
// (softmax normalization moved here).
extern "C" __global__ void __launch_bounds__(256)
sgemm_nt(const float* __restrict__ A, const float* __restrict__ B,
         float* __restrict__ C, int K, int ldn,
         size_t sA, size_t sB, size_t sC,
         const float* __restrict__ sums, size_t sSums)
{
    __shared__ float As[2][8][128];
    __shared__ float Bs[2][8][128];
    const int tid = threadIdx.x;
    const int tx = tid & 15, ty = tid >> 4;
    const int row0 = blockIdx.y * 128, col0 = blockIdx.x * 128;
    const float* Ap = A + (size_t)blockIdx.z * sA + (size_t)row0 * K;
    const float* Bp = B + (size_t)blockIdx.z * sB + (size_t)col0 * K;
    const int ar = tid >> 1, ac = (tid & 1) * 4;

    float acc[8][8];
#pragma unroll
    for (int i = 0; i < 8; i++)
#pragma unroll
        for (int j = 0; j < 8; j++) acc[i][j] = 0.f;

    const int nt = K / 8;
    {
        float4 av = *(const float4*)(Ap + (size_t)ar * K + ac);
        float4 bv = *(const float4*)(Bp + (size_t)ar * K + ac);
        As[0][ac + 0][ar] = av.x; As[0][ac + 1][ar] = av.y;
        As[0][ac + 2][ar] = av.z; As[0][ac + 3][ar] = av.w;
        Bs[0][ac + 0][ar] = bv.x; Bs[0][ac + 1][ar] = bv.y;
        Bs[0][ac + 2][ar] = bv.z; Bs[0][ac + 3][ar] = bv.w;
    }
    __syncthreads();

    for (int t = 0; t < nt; t++) {
        const int cur = t & 1, nxt = cur ^ 1;
        float4 av2, bv2;
        const bool more = (t + 1) < nt;
        if (more) {
            int kt = (t + 1) * 8;
            av2 = *(const float4*)(Ap + (size_t)ar * K + kt + ac);
            bv2 = *(const float4*)(Bp + (size_t)ar * K + kt + ac);
        }
#pragma unroll
        for (int k = 0; k < 8; k++) {
            float a[8], bb[8];
            *(float4*)(a)     = *(const float4*)&As[cur][k][ty * 8];
            *(float4*)(a + 4) = *(const float4*)&As[cur][k][ty * 8 + 4];
            *(float4*)(bb)     = *(const float4*)&Bs[cur][k][tx * 8];
            *(float4*)(bb + 4) = *(const float4*)&Bs[cur][k][tx * 8 + 4];
#pragma unroll
            for (int i = 0; i < 8; i++)
#pragma unroll
                for (int j = 0; j < 8; j++) acc[i][j] += a[i] * bb[j];
        }
        if (more) {
            As[nxt][ac + 0][ar] = av2.x; As[nxt][ac + 1][ar] = av2.y;
            As[nxt][ac + 2][ar] = av2.z; As[nxt][ac + 3][ar] = av2.w;
            Bs[nxt][ac + 0][ar] = bv2.x; Bs[nxt][ac + 1][ar] = bv2.y;
            Bs[nxt][ac + 2][ar] = bv2.z; Bs[nxt][ac + 3][ar] = bv2.w;
        }
        __syncthreads();
    }

    // softmax normalization: divide column n by its exp-row-sum
    float inv[8];
    {
        const float* sp = sums + (size_t)blockIdx.z * sSums + col0 + tx * 8;
        float4 s0 = *(const float4*)(sp);
        float4 s1 = *(const float4*)(sp + 4);
        inv[0] = 1.f / s0.x; inv[1] = 1.f / s0.y;
        inv[2] = 1.f / s0.z; inv[3] = 1.f / s0.w;
        inv[4] = 1.f / s1.x; inv[5] = 1.f / s1.y;
        inv[6] = 1.f / s1.z; inv[7] = 1.f / s1.w;
    }

#pragma unroll
    for (int i = 0; i < 8; i++) {
        int row = row0 + ty * 8 + i;
        size_t off = (size_t)blockIdx.z * sC + (size_t)row * ldn + col0 + tx * 8;
        float o[8];
#pragma unroll
        for (int j = 0; j < 8; j++) o[j] = acc[i][j] * inv[j];
        *(float4*)&C[off]     = *(float4*)(o);
        *(float4*)&C[off + 4] = *(float4*)(o + 4);
    }
}

// ---------------- kernel 3: scores  P = exp(Q @ K), partial row sums --------
// grid (NPIX/64, NPIX/64, BATCH), block 256. k-dim = 32.
// Partial sums go to a unique slot per (row, m-tile): deterministic.
extern "C" __global__ void __launch_bounds__(256)
scores_kernel()
{
    __shared__ float Qs[CRD][64];
    __shared__ float Ks[CRD][64];
    const int b = blockIdx.z;
    const int n0 = blockIdx.y * 64, m0 = blockIdx.x * 64;
    const int tid = threadIdx.x;

#pragma unroll
    for (int it = 0; it < 2; it++) {
        int f = tid + it * 256;            // 0..511 (float4 index)
        int i  = f >> 3;                   // 0..63   n row
        int rr = (f & 7) * 4;              // 0..28
        float4 qv = *(const float4*)&g_Q[((size_t)b * NPIX + n0 + i) * CRD + rr];
        Qs[rr + 0][i] = qv.x; Qs[rr + 1][i] = qv.y;
        Qs[rr + 2][i] = qv.z; Qs[rr + 3][i] = qv.w;
        int r2 = f >> 4;                   // 0..31
        int c2 = (f & 15) * 4;             // 0..60
        *(float4*)&Ks[r2][c2] =
            *(const float4*)&g_K[((size_t)b * CRD + r2) * NPIX + m0 + c2];
    }
    __syncthreads();

    const int tx = tid & 15, ty = tid >> 4;
    float acc[4][4];
#pragma unroll
    for (int i = 0; i < 4; i++)
#pragma unroll
        for (int j = 0; j < 4; j++) acc[i][j] = 0.f;

#pragma unroll
    for (int r = 0; r < CRD; r++) {
        float4 aq = *(const float4*)&Qs[r][ty * 4];
        float4 bk = *(const float4*)&Ks[r][tx * 4];
        float a[4] = {aq.x, aq.y, aq.z, aq.w};
        float bb[4] = {bk.x, bk.y, bk.z, bk.w};
#pragma unroll
        for (int i = 0; i < 4; i++)
#pragma unroll
            for (int j = 0; j < 4; j++) acc[i][j] += a[i] * bb[j];
    }

    // exp() and write P; one deterministic partial-sum slot per (row, m-tile)
#pragma unroll
    for (int i = 0; i < 4; i++) {
        float e[4];
        float psum = 0.f;
#pragma unroll
        for (int j = 0; j < 4; j++) {
            e[j] = __expf(acc[i][j]);
            psum += e[j];
        }
        size_t off = ((size_t)b * NPIX + n0 + ty * 4 + i) * NPIX + m0 + tx * 4;
        *(float4*)&g_P[off] = *(float4*)(e);
        // reduce psum across the 16 tx threads (contiguous half-warp lanes)
#pragma unroll
        for (int o = 8; o > 0; o >>= 1)
            psum += __shfl_xor_sync(0xffffffffu, psum, o);
        if (tx == 0)
            g_Sp[((size_t)b * NPIX + n0 + ty * 4 + i) * MTILES + blockIdx.x] = psum;
    }
}

// ---------------- kernel 4: fold partial sums (warp per row) ----------------
// grid (BATCH*NPIX/8, 1), block 256 (8 warps). Deterministic fixed-order adds.
extern "C" __global__ void __launch_bounds__(256)
reduce_sums_kernel()
{
    const int warp = (blockIdx.x * 256 + threadIdx.x) >> 5;
    const int lane = threadIdx.x & 31;
    if (warp >= BATCH * NPIX) return;
    const float* p = g_Sp + (size_t)warp * MTILES;
    float s = p[lane] + p[lane + 32];
#pragma unroll
    for (int o = 16; o > 0; o >>= 1)
        s += __shfl_xor_sync(0xffffffffu, s, o);
    if (lane == 0) g_S[warp] = s;
}

// ---------------- launcher --------------------------------------------------
extern "C" void kernel_launch(void* const* d_in, const int* in_sizes, int n_in,
                              void* d_out, int out_size)
{
    const float* x     = (const float*)d_in[0];
    const float* Wq    = (const float*)d_in[1];
    const float* bq    = (const float*)d_in[2];
    const float* Wk    = (const float*)d_in[3];
    const float* bk    = (const float*)d_in[4];
    const float* Wv    = (const float*)d_in[5];
    const float* bv    = (const float*)d_in[6];
    const float* Wo    = (const float*)d_in[7];
    const float* bo    = (const float*)d_in[8];
    const float* gamma = (const float*)d_in[9];
    float* out = (float*)d_out;

    void *pV, *pP, *pO, *pS;
    cudaGetSymbolAddress(&pV, g_V);
    cudaGetSymbolAddress(&pP, g_P);
    cudaGetSymbolAddress(&pO, g_O);
    cudaGetSymbolAddress(&pS, g_S);

    cudaFuncSetAttribute(qk_kernel, cudaFuncAttributeMaxDynamicSharedMemorySize,
                         2 * CRD * CCH * (int)sizeof(float));

    const size_t sCN = (size_t)CCH * NPIX;   // per-batch stride for [C,N] maps
    const size_t sNN = (size_t)NPIX * NPIX;  // per-batch stride for P

    // 1) Q,K projections
    {
        dim3 g(NPIX / 256, BATCH);
        qk_kernel<<<g, 256, 2 * CRD * CCH * sizeof(float)>>>(x, Wq, bq, Wk, bk);
    }
    // 2) V = Wv @ x + bv
    {
        dim3 g(NPIX / 128, CCH / 128, BATCH);
        sgemm_nn<<<g, 256>>>(Wv, x, (float*)pV, CCH, NPIX, sCN, sCN,
                             bv, nullptr, nullptr);
    }
    // 3) P = exp(Q @ K), partial row sums
    {
        dim3 g(NPIX / 64, NPIX / 64, BATCH);
        scores_kernel<<<g, 256>>>();
    }
    // 4) fold partial sums into g_S
    {
        reduce_sums_kernel<<<(BATCH * NPIX) / 8, 256>>>();
    }
    // 5) O = (V @ P^T) / sums
    {
        dim3 g(NPIX / 128, CCH / 128, BATCH);
        sgemm_nt<<<g, 256>>>((const float*)pV, (const float*)pP, (float*)pO,
                             NPIX, NPIX, sCN, sNN, sCN,
                             (const float*)pS, (size_t)NPIX);
    }
    // 6) y = gamma * (Wo @ O + bo) + x
    {
        dim3 g(NPIX / 128, CCH / 128, BATCH);
        sgemm_nn<<<g, 256>>>(Wo, (const float*)pO, out, CCH, NPIX, sCN, sCN,
                             bo, x, gamma);
    }
}

// round 9
// speedup vs baseline: 2.9151x; 2.9151x over previous
#include <cuda_runtime.h>
#include <cuda_bf16.h>
#include <math.h>
#include <stdint.h>

#define BATCH 8
#define CCH   512
#define CRD   32
#define NPIX  4096   // 64*64
#define MTILES (NPIX / 64)   // 64 m-tiles per row in scores_kernel
#define KC    32             // k-chunk per smem stage in attn HMMA kernel

// ---------------- scratch (device globals; no allocations allowed) ----------
__device__ float          g_Q [(size_t)BATCH * NPIX * CRD];    // [b][n][r]
__device__ float          g_K [(size_t)BATCH * CRD * NPIX];    // [b][r][m]
__device__ __nv_bfloat16  g_Vh[(size_t)BATCH * CCH * NPIX];    // [b][c][m] bf16
__device__ __nv_bfloat16  g_Ph[(size_t)BATCH * NPIX * NPIX];   // [b][n][m] bf16 exp(S)
__device__ float          g_O [(size_t)BATCH * CCH * NPIX];    // [b][c][n]
__device__ float          g_Sp[(size_t)BATCH * NPIX * MTILES]; // partial row sums
__device__ float          g_S [(size_t)BATCH * NPIX];          // row sums

// ---------------- warp-level tensor-core helpers (base-arch safe) -----------
__device__ __forceinline__ uint32_t smem_u32(const void* p) {
    uint32_t a;
    asm("{ .reg .u64 t; cvta.to.shared.u64 t, %1; cvt.u32.u64 %0, t; }"
        : "=r"(a) : "l"(p));
    return a;
}
__device__ __forceinline__ void ldsm_x4(uint32_t& r0, uint32_t& r1,
                                        uint32_t& r2, uint32_t& r3, uint32_t addr) {
    asm volatile("ldmatrix.sync.aligned.m8n8.x4.shared.b16 {%0,%1,%2,%3}, [%4];"
                 : "=r"(r0), "=r"(r1), "=r"(r2), "=r"(r3) : "r"(addr));
}
__device__ __forceinline__ void ldsm_x2(uint32_t& r0, uint32_t& r1, uint32_t addr) {
    asm volatile("ldmatrix.sync.aligned.m8n8.x2.shared.b16 {%0,%1}, [%2];"
                 : "=r"(r0), "=r"(r1) : "r"(addr));
}
__device__ __forceinline__ void mma_bf16(float* c,
                                         uint32_t a0, uint32_t a1, uint32_t a2, uint32_t a3,
                                         uint32_t b0, uint32_t b1) {
    asm volatile(
        "mma.sync.aligned.m16n8k16.row.col.f32.bf16.bf16.f32 "
        "{%0,%1,%2,%3}, {%4,%5,%6,%7}, {%8,%9}, {%0,%1,%2,%3};"
        : "+f"(c[0]), "+f"(c[1]), "+f"(c[2]), "+f"(c[3])
        : "r"(a0), "r"(a1), "r"(a2), "r"(a3), "r"(b0), "r"(b1));
}

// ---------------- kernel 1: fused Q/K projections ---------------------------
extern "C" __global__ void __launch_bounds__(256)
qk_kernel(const float* __restrict__ x,
          const float* __restrict__ Wq, const float* __restrict__ bq,
          const float* __restrict__ Wk, const float* __restrict__ bk)
{
    extern __shared__ float s_w[];
    float* Wqs = s_w;                 // [CRD][CCH]
    float* Wks = s_w + CRD * CCH;
    const int tid = threadIdx.x;
    for (int i = tid * 4; i < CRD * CCH; i += 256 * 4) {
        *(float4*)&Wqs[i] = *(const float4*)&Wq[i];
        *(float4*)&Wks[i] = *(const float4*)&Wk[i];
    }
    __syncthreads();

    const int b = blockIdx.y;
    const int n = blockIdx.x * 256 + tid;
    const float* xp = x + (size_t)b * CCH * NPIX + n;

    float qa[CRD], ka[CRD];
#pragma unroll
    for (int r = 0; r < CRD; r++) { qa[r] = 0.f; ka[r] = 0.f; }

    for (int c = 0; c < CCH; c += 4) {
        float x0 = xp[(size_t)(c + 0) * NPIX];
        float x1 = xp[(size_t)(c + 1) * NPIX];
        float x2 = xp[(size_t)(c + 2) * NPIX];
        float x3 = xp[(size_t)(c + 3) * NPIX];
#pragma unroll
        for (int r = 0; r < CRD; r++) {
            float4 wq = *(const float4*)&Wqs[r * CCH + c];
            qa[r] += wq.x * x0 + wq.y * x1 + wq.z * x2 + wq.w * x3;
            float4 wk = *(const float4*)&Wks[r * CCH + c];
            ka[r] += wk.x * x0 + wk.y * x1 + wk.z * x2 + wk.w * x3;
        }
    }

    float* qout = g_Q + ((size_t)b * NPIX + n) * CRD;
#pragma unroll
    for (int r = 0; r < CRD; r++) qout[r] = qa[r] + bq[r];
    float* kout = g_K + (size_t)b * CRD * NPIX + n;
#pragma unroll
    for (int r = 0; r < CRD; r++) kout[(size_t)r * NPIX] = ka[r] + bk[r];
}

// ---------------- SGEMM NN  C = A[M,K]*B[K,N]  (fp32 or bf16 out) -----------
extern "C" __global__ void __launch_bounds__(256)
sgemm_nn(const float* __restrict__ A, const float* __restrict__ B,
         float* __restrict__ C, __nv_bfloat16* __restrict__ Ch,
         int K, int ldn, size_t sB, size_t sC,
         const float* __restrict__ bias,
         const float* __restrict__ resid,
         const float* __restrict__ gamma)
{
    __shared__ float As[2][8][128];
    __shared__ float Bs[2][8][128];
    const int tid = threadIdx.x;
    const int tx = tid & 15, ty = tid >> 4;
    const int row0 = blockIdx.y * 128, col0 = blockIdx.x * 128;
    const float* Ap = A + (size_t)row0 * K;
    const float* Bp = B + (size_t)blockIdx.z * sB + col0;
    const int ar = tid >> 1, ac = (tid & 1) * 4;
    const int br = tid >> 5, bc = (tid & 31) * 4;

    float acc[8][8];
#pragma unroll
    for (int i = 0; i < 8; i++)
#pragma unroll
        for (int j = 0; j < 8; j++) acc[i][j] = 0.f;

    const int nt = K / 8;
    {
        float4 av = *(const float4*)(Ap + (size_t)ar * K + ac);
        float4 bv = *(const float4*)(Bp + (size_t)br * ldn + bc);
        As[0][ac + 0][ar] = av.x; As[0][ac + 1][ar] = av.y;
        As[0][ac + 2][ar] = av.z; As[0][ac + 3][ar] = av.w;
        *(float4*)&Bs[0][br][bc] = bv;
    }
    __syncthreads();

    for (int t = 0; t < nt; t++) {
        const int cur = t & 1, nxt = cur ^ 1;
        float4 av2, bv2;
        const bool more = (t + 1) < nt;
        if (more) {
            int kt = (t + 1) * 8;
            av2 = *(const float4*)(Ap + (size_t)ar * K + kt + ac);
            bv2 = *(const float4*)(Bp + (size_t)(kt + br) * ldn + bc);
        }
#pragma unroll
        for (int k = 0; k < 8; k++) {
            float a[8], bb[8];
            *(float4*)(a)     = *(const float4*)&As[cur][k][ty * 8];
            *(float4*)(a + 4) = *(const float4*)&As[cur][k][ty * 8 + 4];
            *(float4*)(bb)     = *(const float4*)&Bs[cur][k][tx * 8];
            *(float4*)(bb + 4) = *(const float4*)&Bs[cur][k][tx * 8 + 4];
#pragma unroll
            for (int i = 0; i < 8; i++)
#pragma unroll
                for (int j = 0; j < 8; j++) acc[i][j] += a[i] * bb[j];
        }
        if (more) {
            As[nxt][ac + 0][ar] = av2.x; As[nxt][ac + 1][ar] = av2.y;
            As[nxt][ac + 2][ar] = av2.z; As[nxt][ac + 3][ar] = av2.w;
            *(float4*)&Bs[nxt][br][bc] = bv2;
        }
        __syncthreads();
    }

    const float g = gamma ? *gamma : 0.f;
#pragma unroll
    for (int i = 0; i < 8; i++) {
        int row = row0 + ty * 8 + i;
        float bval = bias ? bias[row] : 0.f;
        size_t off = (size_t)blockIdx.z * sC + (size_t)row * ldn + col0 + tx * 8;
        float o[8];
#pragma unroll
        for (int j = 0; j < 8; j++) {
            float v = acc[i][j] + bval;
            if (resid) v = g * v + resid[off + j];
            o[j] = v;
        }
        if (Ch) {
            __nv_bfloat162 h[4];
#pragma unroll
            for (int j = 0; j < 4; j++)
                h[j] = __nv_bfloat162(__float2bfloat16_rn(o[2 * j]),
                                      __float2bfloat16_rn(o[2 * j + 1]));
            *(uint4*)&Ch[off] = *(uint4*)h;
        } else {
            *(float4*)&C[off]     = *(float4*)(o);
            *(float4*)&C[off + 4] = *(float4*)(o + 4);
        }
    }
}

// ---------------- kernel 3: scores  P = bf16(exp(Q @ K)), partial sums ------
extern "C" __global__ void __launch_bounds__(256)
scores_kernel()
{
    __shared__ float Qs[CRD][64];
    __shared__ float Ks[CRD][64];
    const int b = blockIdx.z;
    const int n0 = blockIdx.y * 64, m0 = blockIdx.x * 64;
    const int tid = threadIdx.x;

#pragma unroll
    for (int it = 0; it < 2; it++) {
        int f = tid + it * 256;
        int i  = f >> 3;
        int rr = (f & 7) * 4;
        float4 qv = *(const float4*)&g_Q[((size_t)b * NPIX + n0 + i) * CRD + rr];
        Qs[rr + 0][i] = qv.x; Qs[rr + 1][i] = qv.y;
        Qs[rr + 2][i] = qv.z; Qs[rr + 3][i] = qv.w;
        int r2 = f >> 4;
        int c2 = (f & 15) * 4;
        *(float4*)&Ks[r2][c2] =
            *(const float4*)&g_K[((size_t)b * CRD + r2) * NPIX + m0 + c2];
    }
    __syncthreads();

    const int tx = tid & 15, ty = tid >> 4;
    float acc[4][4];
#pragma unroll
    for (int i = 0; i < 4; i++)
#pragma unroll
        for (int j = 0; j < 4; j++) acc[i][j] = 0.f;

#pragma unroll
    for (int r = 0; r < CRD; r++) {
        float4 aq = *(const float4*)&Qs[r][ty * 4];
        float4 bk = *(const float4*)&Ks[r][tx * 4];
        float a[4] = {aq.x, aq.y, aq.z, aq.w};
        float bb[4] = {bk.x, bk.y, bk.z, bk.w};
#pragma unroll
        for (int i = 0; i < 4; i++)
#pragma unroll
            for (int j = 0; j < 4; j++) acc[i][j] += a[i] * bb[j];
    }

#pragma unroll
    for (int i = 0; i < 4; i++) {
        __nv_bfloat16 e[4];
        float psum = 0.f;
#pragma unroll
        for (int j = 0; j < 4; j++) {
            e[j] = __float2bfloat16_rn(__expf(acc[i][j]));
            psum += __bfloat162float(e[j]);   // sum exactly what the MMA sums
        }
        size_t off = ((size_t)b * NPIX + n0 + ty * 4 + i) * NPIX + m0 + tx * 4;
        *(uint2*)&g_Ph[off] = *(uint2*)e;
#pragma unroll
        for (int o = 8; o > 0; o >>= 1)
            psum += __shfl_xor_sync(0xffffffffu, psum, o);
        if (tx == 0)
            g_Sp[((size_t)b * NPIX + n0 + ty * 4 + i) * MTILES + blockIdx.x] = psum;
    }
}

// ---------------- kernel 4: fold partial sums (warp per row) ----------------
extern "C" __global__ void __launch_bounds__(256)
reduce_sums_kernel()
{
    const int warp = (blockIdx.x * 256 + threadIdx.x) >> 5;
    const int lane = threadIdx.x & 31;
    if (warp >= BATCH * NPIX) return;
    const float* p = g_Sp + (size_t)warp * MTILES;
    float s = p[lane] + p[lane + 32];
#pragma unroll
    for (int o = 16; o > 0; o >>= 1)
        s += __shfl_xor_sync(0xffffffffu, s, o);
    if (lane == 0) g_S[warp] = s;
}

// ---------------- kernel 5: HMMA bf16  O = (V @ P^T) / sums -----------------
// grid (NPIX/128, CCH/128, BATCH), block 256 (8 warps, 2x4).
// A = V[c,m] (row operand), B = P[n,m] (col operand, k contiguous).
extern "C" __global__ void __launch_bounds__(256)
attn_mma_kernel()
{
    __shared__ __nv_bfloat16 As[2][128][KC + 8];   // +8 pad: conflict-free ldmatrix
    __shared__ __nv_bfloat16 Bs[2][128][KC + 8];
    __shared__ float s_inv[128];

    const int tid  = threadIdx.x;
    const int wid  = tid >> 5;
    const int lane = tid & 31;
    const int b    = blockIdx.z;
    const int row0 = blockIdx.y * 128;   // channel tile
    const int n0   = blockIdx.x * 128;   // pixel tile
    const int wm   = wid >> 2;           // 0..1  (64-row slab)
    const int wn   = wid & 3;            // 0..3  (32-col slab)

    if (tid < 128) s_inv[tid] = 1.f / g_S[(size_t)b * NPIX + n0 + tid];

    const __nv_bfloat16* Ag = g_Vh + ((size_t)b * CCH  + row0) * NPIX;
    const __nv_bfloat16* Bg = g_Ph + ((size_t)b * NPIX + n0)  * NPIX;

    float acc[4][4][4];
#pragma unroll
    for (int i = 0; i < 4; i++)
#pragma unroll
        for (int j = 0; j < 4; j++)
#pragma unroll
            for (int k = 0; k < 4; k++) acc[i][j][k] = 0.f;

    const int r_ld = tid >> 2;           // 0..63? no: tid/4 -> 0..63 for 256thr? tid>>2: 0..63
    // each thread loads 2 rows' quarters: idx = t*256+tid -> r = idx>>2 (0..127), q = idx&3
    const int NT = NPIX / KC;            // 128 stages
    (void)r_ld;

    // prologue: stage 0
#pragma unroll
    for (int t = 0; t < 2; t++) {
        int idx = t * 256 + tid;
        int r = idx >> 2, q = idx & 3;
        *(uint4*)&As[0][r][q * 8] = *(const uint4*)&Ag[(size_t)r * NPIX + q * 8];
        *(uint4*)&Bs[0][r][q * 8] = *(const uint4*)&Bg[(size_t)r * NPIX + q * 8];
    }
    __syncthreads();

    for (int kt = 0; kt < NT; kt++) {
        const int s = kt & 1;
        uint4 pa[2], pb[2];
        const bool more = (kt + 1) < NT;
        if (more) {
            const int k0 = (kt + 1) * KC;
#pragma unroll
            for (int t = 0; t < 2; t++) {
                int idx = t * 256 + tid;
                int r = idx >> 2, q = idx & 3;
                pa[t] = *(const uint4*)&Ag[(size_t)r * NPIX + k0 + q * 8];
                pb[t] = *(const uint4*)&Bg[(size_t)r * NPIX + k0 + q * 8];
            }
        }
        // compute on stage s: 2 k16 steps
#pragma unroll
        for (int ks = 0; ks < 2; ks++) {
            uint32_t af[4][4];
#pragma unroll
            for (int mi = 0; mi < 4; mi++) {
                uint32_t addr = smem_u32(
                    &As[s][wm * 64 + mi * 16 + (lane & 15)][ks * 16 + (lane >> 4) * 8]);
                ldsm_x4(af[mi][0], af[mi][1], af[mi][2], af[mi][3], addr);
            }
            uint32_t bf[4][2];
#pragma unroll
            for (int ni = 0; ni < 4; ni++) {
                uint32_t addr = smem_u32(
                    &Bs[s][wn * 32 + ni * 8 + (lane & 7)][ks * 16 + ((lane >> 3) & 1) * 8]);
                ldsm_x2(bf[ni][0], bf[ni][1], addr);
            }
#pragma unroll
            for (int mi = 0; mi < 4; mi++)
#pragma unroll
                for (int ni = 0; ni < 4; ni++)
                    mma_bf16(acc[mi][ni],
                             af[mi][0], af[mi][1], af[mi][2], af[mi][3],
                             bf[ni][0], bf[ni][1]);
        }
        if (more) {
            const int ns = s ^ 1;
#pragma unroll
            for (int t = 0; t < 2; t++) {
                int idx = t * 256 + tid;
                int r = idx >> 2, q = idx & 3;
                *(uint4*)&As[ns][r][q * 8] = pa[t];
                *(uint4*)&Bs[ns][r][q * 8] = pb[t];
            }
        }
        __syncthreads();
    }

    // epilogue: normalize by 1/rowsum (per pixel column n), store fp32 O
#pragma unroll
    for (int mi = 0; mi < 4; mi++) {
#pragma unroll
        for (int ni = 0; ni < 4; ni++) {
            int mrow = row0 + wm * 64 + mi * 16 + (lane >> 2);
            int nl   = wn * 32 + ni * 8 + (lane & 3) * 2;
            float i0 = s_inv[nl], i1 = s_inv[nl + 1];
            float2 v0 = make_float2(acc[mi][ni][0] * i0, acc[mi][ni][1] * i1);
            float2 v1 = make_float2(acc[mi][ni][2] * i0, acc[mi][ni][3] * i1);
            *(float2*)&g_O[((size_t)b * CCH + mrow) * NPIX + n0 + nl]     = v0;
            *(float2*)&g_O[((size_t)b * CCH + mrow + 8) * NPIX + n0 + nl] = v1;
        }
    }
}

// ---------------- launcher --------------------------------------------------
extern "C" void kernel_launch(void* const* d_in, const int* in_sizes, int n_in,
                              void* d_out, int out_size)
{
    const float* x     = (const float*)d_in[0];
    const float* Wq    = (const float*)d_in[1];
    const float* bq    = (const float*)d_in[2];
    const float* Wk    = (const float*)d_in[3];
    const float* bk    = (const float*)d_in[4];
    const float* Wv    = (const float*)d_in[5];
    const float* bv    = (const float*)d_in[6];
    const float* Wo    = (const float*)d_in[7];
    const float* bo    = (const float*)d_in[8];
    const float* gamma = (const float*)d_in[9];
    float* out = (float*)d_out;

    void *pVh, *pO;
    cudaGetSymbolAddress(&pVh, g_Vh);
    cudaGetSymbolAddress(&pO, g_O);

    cudaFuncSetAttribute(qk_kernel, cudaFuncAttributeMaxDynamicSharedMemorySize,
                         2 * CRD * CCH * (int)sizeof(float));

    const size_t sCN = (size_t)CCH * NPIX;

    // 1) Q,K projections
    {
        dim3 g(NPIX / 256, BATCH);
        qk_kernel<<<g, 256, 2 * CRD * CCH * sizeof(float)>>>(x, Wq, bq, Wk, bk);
    }
    // 2) V = bf16(Wv @ x + bv)
    {
        dim3 g(NPIX / 128, CCH / 128, BATCH);
        sgemm_nn<<<g, 256>>>(Wv, x, nullptr, (__nv_bfloat16*)pVh,
                             CCH, NPIX, sCN, sCN, bv, nullptr, nullptr);
    }
    // 3) P = bf16(exp(Q @ K)), partial row sums
    {
        dim3 g(NPIX / 64, NPIX / 64, BATCH);
        scores_kernel<<<g, 256>>>();
    }
    // 4) fold partial sums
    reduce_sums_kernel<<<(BATCH * NPIX) / 8, 256>>>();
    // 5) O = (V @ P^T) / sums   — HMMA bf16
    {
        dim3 g(NPIX / 128, CCH / 128, BATCH);
        attn_mma_kernel<<<g, 256>>>();
    }
    // 6) y = gamma * (Wo @ O + bo) + x
    {
        dim3 g(NPIX / 128, CCH / 128, BATCH);
        sgemm_nn<<<g, 256>>>(Wo, (const float*)pO, out, nullptr,
                             CCH, NPIX, sCN, sCN, bo, x, gamma);
    }
}

// round 10
// speedup vs baseline: 4.4574x; 1.5291x over previous
#include <cuda_runtime.h>
#include <cuda_bf16.h>
#include <math.h>
#include <stdint.h>

#define BATCH 8
#define CCH   512
#define CRD   32
#define NPIX  4096   // 64*64
#define MTILES (NPIX / 64)   // 64 m-tiles per row in scores_kernel
#define KC    32             // k-chunk per smem stage in HMMA kernels

// ---------------- scratch (device globals; no allocations allowed) ----------
__device__ float          g_Q  [(size_t)BATCH * NPIX * CRD];    // [b][n][r]
__device__ float          g_K  [(size_t)BATCH * CRD * NPIX];    // [b][r][m]
__device__ __nv_bfloat16  g_Vh [(size_t)BATCH * CCH * NPIX];    // [b][c][m] bf16
__device__ __nv_bfloat16  g_Ph [(size_t)BATCH * NPIX * NPIX];   // [b][n][m] bf16 exp(S)
__device__ __nv_bfloat16  g_OTh[(size_t)BATCH * NPIX * CCH];    // [b][n][c] bf16 attn out
__device__ __nv_bfloat16  g_xTh[(size_t)BATCH * NPIX * CCH];    // [b][n][c] bf16 x^T
__device__ __nv_bfloat16  g_Wvh[(size_t)CCH * CCH];             // bf16 Wv
__device__ __nv_bfloat16  g_Woh[(size_t)CCH * CCH];             // bf16 Wo
__device__ float          g_Sp [(size_t)BATCH * NPIX * MTILES]; // partial row sums
__device__ float          g_S  [(size_t)BATCH * NPIX];          // row sums

// ---------------- warp-level tensor-core helpers (base-arch safe) -----------
__device__ __forceinline__ uint32_t smem_u32(const void* p) {
    uint32_t a;
    asm("{ .reg .u64 t; cvta.to.shared.u64 t, %1; cvt.u32.u64 %0, t; }"
        : "=r"(a) : "l"(p));
    return a;
}
__device__ __forceinline__ void ldsm_x4(uint32_t& r0, uint32_t& r1,
                                        uint32_t& r2, uint32_t& r3, uint32_t addr) {
    asm volatile("ldmatrix.sync.aligned.m8n8.x4.shared.b16 {%0,%1,%2,%3}, [%4];"
                 : "=r"(r0), "=r"(r1), "=r"(r2), "=r"(r3) : "r"(addr));
}
__device__ __forceinline__ void ldsm_x2(uint32_t& r0, uint32_t& r1, uint32_t addr) {
    asm volatile("ldmatrix.sync.aligned.m8n8.x2.shared.b16 {%0,%1}, [%2];"
                 : "=r"(r0), "=r"(r1) : "r"(addr));
}
__device__ __forceinline__ void mma_bf16(float* c,
                                         uint32_t a0, uint32_t a1, uint32_t a2, uint32_t a3,
                                         uint32_t b0, uint32_t b1) {
    asm volatile(
        "mma.sync.aligned.m16n8k16.row.col.f32.bf16.bf16.f32 "
        "{%0,%1,%2,%3}, {%4,%5,%6,%7}, {%8,%9}, {%0,%1,%2,%3};"
        : "+f"(c[0]), "+f"(c[1]), "+f"(c[2]), "+f"(c[3])
        : "r"(a0), "r"(a1), "r"(a2), "r"(a3), "r"(b0), "r"(b1));
}

// ---------------- kernel 0a: weights -> bf16 --------------------------------
extern "C" __global__ void __launch_bounds__(256)
convert_w_kernel(const float* __restrict__ Wv, const float* __restrict__ Wo)
{
    int i = blockIdx.x * 256 + threadIdx.x;
    if (i < CCH * CCH) {
        g_Wvh[i] = __float2bfloat16_rn(Wv[i]);
        g_Woh[i] = __float2bfloat16_rn(Wo[i]);
    }
}

// ---------------- kernel 0b: x -> x^T bf16 ----------------------------------
// grid (NPIX/32, CCH/32, BATCH), block (32,8)
extern "C" __global__ void __launch_bounds__(256)
transpose_x_kernel(const float* __restrict__ x)
{
    __shared__ float tile[32][33];
    const int b = blockIdx.z;
    const int n0 = blockIdx.x * 32, c0 = blockIdx.y * 32;
    const int tx = threadIdx.x, ty = threadIdx.y;
#pragma unroll
    for (int j = 0; j < 4; j++)
        tile[ty + j * 8][tx] = x[((size_t)b * CCH + c0 + ty + j * 8) * NPIX + n0 + tx];
    __syncthreads();
#pragma unroll
    for (int j = 0; j < 4; j++)
        g_xTh[((size_t)b * NPIX + n0 + ty + j * 8) * CCH + c0 + tx] =
            __float2bfloat16_rn(tile[tx][ty + j * 8]);
}

// ---------------- kernel 1: fused Q/K projections (fp32) --------------------
extern "C" __global__ void __launch_bounds__(256)
qk_kernel(const float* __restrict__ x,
          const float* __restrict__ Wq, const float* __restrict__ bq,
          const float* __restrict__ Wk, const float* __restrict__ bk)
{
    extern __shared__ float s_w[];
    float* Wqs = s_w;                 // [CRD][CCH]
    float* Wks = s_w + CRD * CCH;
    const int tid = threadIdx.x;
    for (int i = tid * 4; i < CRD * CCH; i += 256 * 4) {
        *(float4*)&Wqs[i] = *(const float4*)&Wq[i];
        *(float4*)&Wks[i] = *(const float4*)&Wk[i];
    }
    __syncthreads();

    const int b = blockIdx.y;
    const int n = blockIdx.x * 256 + tid;
    const float* xp = x + (size_t)b * CCH * NPIX + n;

    float qa[CRD], ka[CRD];
#pragma unroll
    for (int r = 0; r < CRD; r++) { qa[r] = 0.f; ka[r] = 0.f; }

    for (int c = 0; c < CCH; c += 4) {
        float x0 = xp[(size_t)(c + 0) * NPIX];
        float x1 = xp[(size_t)(c + 1) * NPIX];
        float x2 = xp[(size_t)(c + 2) * NPIX];
        float x3 = xp[(size_t)(c + 3) * NPIX];
#pragma unroll
        for (int r = 0; r < CRD; r++) {
            float4 wq = *(const float4*)&Wqs[r * CCH + c];
            qa[r] += wq.x * x0 + wq.y * x1 + wq.z * x2 + wq.w * x3;
            float4 wk = *(const float4*)&Wks[r * CCH + c];
            ka[r] += wk.x * x0 + wk.y * x1 + wk.z * x2 + wk.w * x3;
        }
    }

    float* qout = g_Q + ((size_t)b * NPIX + n) * CRD;
#pragma unroll
    for (int r = 0; r < CRD; r++) qout[r] = qa[r] + bq[r];
    float* kout = g_K + (size_t)b * CRD * NPIX + n;
#pragma unroll
    for (int r = 0; r < CRD; r++) kout[(size_t)r * NPIX] = ka[r] + bk[r];
}

// ---------------- kernel 3: scores  P = bf16(exp(Q @ K)), partial sums ------
extern "C" __global__ void __launch_bounds__(256)
scores_kernel()
{
    __shared__ float Qs[CRD][64];
    __shared__ float Ks[CRD][64];
    const int b = blockIdx.z;
    const int n0 = blockIdx.y * 64, m0 = blockIdx.x * 64;
    const int tid = threadIdx.x;

#pragma unroll
    for (int it = 0; it < 2; it++) {
        int f = tid + it * 256;
        int i  = f >> 3;
        int rr = (f & 7) * 4;
        float4 qv = *(const float4*)&g_Q[((size_t)b * NPIX + n0 + i) * CRD + rr];
        Qs[rr + 0][i] = qv.x; Qs[rr + 1][i] = qv.y;
        Qs[rr + 2][i] = qv.z; Qs[rr + 3][i] = qv.w;
        int r2 = f >> 4;
        int c2 = (f & 15) * 4;
        *(float4*)&Ks[r2][c2] =
            *(const float4*)&g_K[((size_t)b * CRD + r2) * NPIX + m0 + c2];
    }
    __syncthreads();

    const int tx = tid & 15, ty = tid >> 4;
    float acc[4][4];
#pragma unroll
    for (int i = 0; i < 4; i++)
#pragma unroll
        for (int j = 0; j < 4; j++) acc[i][j] = 0.f;

#pragma unroll
    for (int r = 0; r < CRD; r++) {
        float4 aq = *(const float4*)&Qs[r][ty * 4];
        float4 bk = *(const float4*)&Ks[r][tx * 4];
        float a[4] = {aq.x, aq.y, aq.z, aq.w};
        float bb[4] = {bk.x, bk.y, bk.z, bk.w};
#pragma unroll
        for (int i = 0; i < 4; i++)
#pragma unroll
            for (int j = 0; j < 4; j++) acc[i][j] += a[i] * bb[j];
    }

#pragma unroll
    for (int i = 0; i < 4; i++) {
        __nv_bfloat16 e[4];
        float psum = 0.f;
#pragma unroll
        for (int j = 0; j < 4; j++) {
            e[j] = __float2bfloat16_rn(__expf(acc[i][j]));
            psum += __bfloat162float(e[j]);   // sum exactly what the MMA sums
        }
        size_t off = ((size_t)b * NPIX + n0 + ty * 4 + i) * NPIX + m0 + tx * 4;
        *(uint2*)&g_Ph[off] = *(uint2*)e;
#pragma unroll
        for (int o = 8; o > 0; o >>= 1)
            psum += __shfl_xor_sync(0xffffffffu, psum, o);
        if (tx == 0)
            g_Sp[((size_t)b * NPIX + n0 + ty * 4 + i) * MTILES + blockIdx.x] = psum;
    }
}

// ---------------- kernel 4: fold partial sums (warp per row) ----------------
extern "C" __global__ void __launch_bounds__(256)
reduce_sums_kernel()
{
    const int warp = (blockIdx.x * 256 + threadIdx.x) >> 5;
    const int lane = threadIdx.x & 31;
    if (warp >= BATCH * NPIX) return;
    const float* p = g_Sp + (size_t)warp * MTILES;
    float s = p[lane] + p[lane + 32];
#pragma unroll
    for (int o = 16; o > 0; o >>= 1)
        s += __shfl_xor_sync(0xffffffffu, s, o);
    if (lane == 0) g_S[warp] = s;
}

// ---------------- kernel 5: HMMA bf16  O^T = ((V @ P^T)/sums)^T -------------
// grid (NPIX/128, CCH/128, BATCH), block 256 (8 warps, 2x4).
// A = V[c,m] (row operand), B = P[n,m] (col operand). Out: g_OTh [n][c] bf16.
// Dynamic smem 40KB: 2 stages A+B; epilogue reuses it as T[128][136] bf16.
#define ATT_STAGE (128 * (KC + 8))        // elements per operand stage
extern "C" __global__ void __launch_bounds__(256)
attn_mma_kernel()
{
    extern __shared__ __align__(16) __nv_bfloat16 dynsm[];
    __nv_bfloat16* Asb = dynsm;                  // [2][128][KC+8]
    __nv_bfloat16* Bsb = dynsm + 2 * ATT_STAGE;  // [2][128][KC+8]
    __shared__ float s_inv[128];
#define AS(s, r, k) Asb[((s) * 128 + (r)) * (KC + 8) + (k)]
#define BS(s, r, k) Bsb[((s) * 128 + (r)) * (KC + 8) + (k)]

    const int tid  = threadIdx.x;
    const int wid  = tid >> 5;
    const int lane = tid & 31;
    const int b    = blockIdx.z;
    const int row0 = blockIdx.y * 128;   // channel tile
    const int n0   = blockIdx.x * 128;   // pixel tile
    const int wm   = wid >> 2;           // 0..1
    const int wn   = wid & 3;            // 0..3

    if (tid < 128) s_inv[tid] = 1.f / g_S[(size_t)b * NPIX + n0 + tid];

    const __nv_bfloat16* Ag = g_Vh + ((size_t)b * CCH  + row0) * NPIX;
    const __nv_bfloat16* Bg = g_Ph + ((size_t)b * NPIX + n0)  * NPIX;

    float acc[4][4][4];
#pragma unroll
    for (int i = 0; i < 4; i++)
#pragma unroll
        for (int j = 0; j < 4; j++)
#pragma unroll
            for (int k = 0; k < 4; k++) acc[i][j][k] = 0.f;

    const int NT = NPIX / KC;            // 128 stages

#pragma unroll
    for (int t = 0; t < 2; t++) {
        int idx = t * 256 + tid;
        int r = idx >> 2, q = idx & 3;
        *(uint4*)&AS(0, r, q * 8) = *(const uint4*)&Ag[(size_t)r * NPIX + q * 8];
        *(uint4*)&BS(0, r, q * 8) = *(const uint4*)&Bg[(size_t)r * NPIX + q * 8];
    }
    __syncthreads();

    for (int kt = 0; kt < NT; kt++) {
        const int s = kt & 1;
        uint4 pa[2], pb[2];
        const bool more = (kt + 1) < NT;
        if (more) {
            const int k0 = (kt + 1) * KC;
#pragma unroll
            for (int t = 0; t < 2; t++) {
                int idx = t * 256 + tid;
                int r = idx >> 2, q = idx & 3;
                pa[t] = *(const uint4*)&Ag[(size_t)r * NPIX + k0 + q * 8];
                pb[t] = *(const uint4*)&Bg[(size_t)r * NPIX + k0 + q * 8];
            }
        }
#pragma unroll
        for (int ks = 0; ks < 2; ks++) {
            uint32_t af[4][4];
#pragma unroll
            for (int mi = 0; mi < 4; mi++) {
                uint32_t addr = smem_u32(
                    &AS(s, wm * 64 + mi * 16 + (lane & 15), ks * 16 + (lane >> 4) * 8));
                ldsm_x4(af[mi][0], af[mi][1], af[mi][2], af[mi][3], addr);
            }
            uint32_t bf[4][2];
#pragma unroll
            for (int ni = 0; ni < 4; ni++) {
                uint32_t addr = smem_u32(
                    &BS(s, wn * 32 + ni * 8 + (lane & 7), ks * 16 + ((lane >> 3) & 1) * 8));
                ldsm_x2(bf[ni][0], bf[ni][1], addr);
            }
#pragma unroll
            for (int mi = 0; mi < 4; mi++)
#pragma unroll
                for (int ni = 0; ni < 4; ni++)
                    mma_bf16(acc[mi][ni],
                             af[mi][0], af[mi][1], af[mi][2], af[mi][3],
                             bf[ni][0], bf[ni][1]);
        }
        if (more) {
            const int ns = s ^ 1;
#pragma unroll
            for (int t = 0; t < 2; t++) {
                int idx = t * 256 + tid;
                int r = idx >> 2, q = idx & 3;
                *(uint4*)&AS(ns, r, q * 8) = pa[t];
                *(uint4*)&BS(ns, r, q * 8) = pb[t];
            }
        }
        __syncthreads();
    }

    // epilogue: normalize, transpose via smem, write O^T [n][c] bf16
    __nv_bfloat16* T = dynsm;   // [128][136]
#pragma unroll
    for (int mi = 0; mi < 4; mi++) {
#pragma unroll
        for (int ni = 0; ni < 4; ni++) {
            int ml = wm * 64 + mi * 16 + (lane >> 2);
            int nl = wn * 32 + ni * 8 + (lane & 3) * 2;
            float i0 = s_inv[nl], i1 = s_inv[nl + 1];
            T[nl * 136 + ml]           = __float2bfloat16_rn(acc[mi][ni][0] * i0);
            T[(nl + 1) * 136 + ml]     = __float2bfloat16_rn(acc[mi][ni][1] * i1);
            T[nl * 136 + ml + 8]       = __float2bfloat16_rn(acc[mi][ni][2] * i0);
            T[(nl + 1) * 136 + ml + 8] = __float2bfloat16_rn(acc[mi][ni][3] * i1);
        }
    }
    __syncthreads();
#pragma unroll
    for (int t = 0; t < 8; t++) {
        int idx = t * 256 + tid;
        int r = idx >> 4, q = idx & 15;
        *(uint4*)&g_OTh[((size_t)b * NPIX + n0 + r) * CCH + row0 + q * 8] =
            *(uint4*)&T[r * 136 + q * 8];
    }
#undef AS
#undef BS
}

// ---------------- kernel 2/6: HMMA bf16 projection  C = W @ X ---------------
// grid (NPIX/128, M/128, BATCH), block 256. W [M,K] bf16 row-major,
// Bt [b][NPIX,K] bf16 (k contiguous). Out bf16 [c][n] (Ch) or fp32 with
// gamma/resid epilogue (Cf). bias always present (per output row).
extern "C" __global__ void __launch_bounds__(256)
proj_mma_kernel(const __nv_bfloat16* __restrict__ W,
                const __nv_bfloat16* __restrict__ Bt,
                __nv_bfloat16* __restrict__ Ch,
                float* __restrict__ Cf,
                const float* __restrict__ bias,
                const float* __restrict__ resid,
                const float* __restrict__ gamma,
                int K)
{
    __shared__ __nv_bfloat16 As[2][128][KC + 8];
    __shared__ __nv_bfloat16 Bs[2][128][KC + 8];

    const int tid  = threadIdx.x;
    const int wid  = tid >> 5;
    const int lane = tid & 31;
    const int b    = blockIdx.z;
    const int row0 = blockIdx.y * 128;
    const int n0   = blockIdx.x * 128;
    const int wm   = wid >> 2;
    const int wn   = wid & 3;

    const __nv_bfloat16* Ag = W + (size_t)row0 * K;
    const __nv_bfloat16* Bg = Bt + ((size_t)b * NPIX + n0) * K;

    float acc[4][4][4];
#pragma unroll
    for (int i = 0; i < 4; i++)
#pragma unroll
        for (int j = 0; j < 4; j++)
#pragma unroll
            for (int k = 0; k < 4; k++) acc[i][j][k] = 0.f;

    const int NT = K / KC;

#pragma unroll
    for (int t = 0; t < 2; t++) {
        int idx = t * 256 + tid;
        int r = idx >> 2, q = idx & 3;
        *(uint4*)&As[0][r][q * 8] = *(const uint4*)&Ag[(size_t)r * K + q * 8];
        *(uint4*)&Bs[0][r][q * 8] = *(const uint4*)&Bg[(size_t)r * K + q * 8];
    }
    __syncthreads();

    for (int kt = 0; kt < NT; kt++) {
        const int s = kt & 1;
        uint4 pa[2], pb[2];
        const bool more = (kt + 1) < NT;
        if (more) {
            const int k0 = (kt + 1) * KC;
#pragma unroll
            for (int t = 0; t < 2; t++) {
                int idx = t * 256 + tid;
                int r = idx >> 2, q = idx & 3;
                pa[t] = *(const uint4*)&Ag[(size_t)r * K + k0 + q * 8];
                pb[t] = *(const uint4*)&Bg[(size_t)r * K + k0 + q * 8];
            }
        }
#pragma unroll
        for (int ks = 0; ks < 2; ks++) {
            uint32_t af[4][4];
#pragma unroll
            for (int mi = 0; mi < 4; mi++) {
                uint32_t addr = smem_u32(
                    &As[s][wm * 64 + mi * 16 + (lane & 15)][ks * 16 + (lane >> 4) * 8]);
                ldsm_x4(af[mi][0], af[mi][1], af[mi][2], af[mi][3], addr);
            }
            uint32_t bf[4][2];
#pragma unroll
            for (int ni = 0; ni < 4; ni++) {
                uint32_t addr = smem_u32(
                    &Bs[s][wn * 32 + ni * 8 + (lane & 7)][ks * 16 + ((lane >> 3) & 1) * 8]);
                ldsm_x2(bf[ni][0], bf[ni][1], addr);
            }
#pragma unroll
            for (int mi = 0; mi < 4; mi++)
#pragma unroll
                for (int ni = 0; ni < 4; ni++)
                    mma_bf16(acc[mi][ni],
                             af[mi][0], af[mi][1], af[mi][2], af[mi][3],
                             bf[ni][0], bf[ni][1]);
        }
        if (more) {
            const int ns = s ^ 1;
#pragma unroll
            for (int t = 0; t < 2; t++) {
                int idx = t * 256 + tid;
                int r = idx >> 2, q = idx & 3;
                *(uint4*)&As[ns][r][q * 8] = pa[t];
                *(uint4*)&Bs[ns][r][q * 8] = pb[t];
            }
        }
        __syncthreads();
    }

    const float g = gamma ? *gamma : 0.f;
#pragma unroll
    for (int mi = 0; mi < 4; mi++) {
#pragma unroll
        for (int ni = 0; ni < 4; ni++) {
            int mrow = row0 + wm * 64 + mi * 16 + (lane >> 2);
            int nl   = n0 + wn * 32 + ni * 8 + (lane & 3) * 2;
            float b0 = bias[mrow], b1 = bias[mrow + 8];
            float v00 = acc[mi][ni][0] + b0, v01 = acc[mi][ni][1] + b0;
            float v10 = acc[mi][ni][2] + b1, v11 = acc[mi][ni][3] + b1;
            size_t off0 = ((size_t)b * CCH + mrow) * NPIX + nl;
            size_t off1 = ((size_t)b * CCH + mrow + 8) * NPIX + nl;
            if (Cf) {
                v00 = g * v00 + resid[off0];     v01 = g * v01 + resid[off0 + 1];
                v10 = g * v10 + resid[off1];     v11 = g * v11 + resid[off1 + 1];
                *(float2*)&Cf[off0] = make_float2(v00, v01);
                *(float2*)&Cf[off1] = make_float2(v10, v11);
            } else {
                __nv_bfloat162 h0(__float2bfloat16_rn(v00), __float2bfloat16_rn(v01));
                __nv_bfloat162 h1(__float2bfloat16_rn(v10), __float2bfloat16_rn(v11));
                *(__nv_bfloat162*)&Ch[off0] = h0;
                *(__nv_bfloat162*)&Ch[off1] = h1;
            }
        }
    }
}

// ---------------- launcher --------------------------------------------------
extern "C" void kernel_launch(void* const* d_in, const int* in_sizes, int n_in,
                              void* d_out, int out_size)
{
    const float* x     = (const float*)d_in[0];
    const float* Wq    = (const float*)d_in[1];
    const float* bq    = (const float*)d_in[2];
    const float* Wk    = (const float*)d_in[3];
    const float* bk    = (const float*)d_in[4];
    const float* Wv    = (const float*)d_in[5];
    const float* bv    = (const float*)d_in[6];
    const float* Wo    = (const float*)d_in[7];
    const float* bo    = (const float*)d_in[8];
    const float* gamma = (const float*)d_in[9];
    float* out = (float*)d_out;

    void *pVh, *pOTh, *pxTh, *pWvh, *pWoh;
    cudaGetSymbolAddress(&pVh, g_Vh);
    cudaGetSymbolAddress(&pOTh, g_OTh);
    cudaGetSymbolAddress(&pxTh, g_xTh);
    cudaGetSymbolAddress(&pWvh, g_Wvh);
    cudaGetSymbolAddress(&pWoh, g_Woh);

    cudaFuncSetAttribute(qk_kernel, cudaFuncAttributeMaxDynamicSharedMemorySize,
                         2 * CRD * CCH * (int)sizeof(float));
    cudaFuncSetAttribute(attn_mma_kernel, cudaFuncAttributeMaxDynamicSharedMemorySize,
                         4 * ATT_STAGE * (int)sizeof(__nv_bfloat16));

    // 0) weights -> bf16 ; x -> x^T bf16
    convert_w_kernel<<<(CCH * CCH + 255) / 256, 256>>>(Wv, Wo);
    {
        dim3 g(NPIX / 32, CCH / 32, BATCH);
        transpose_x_kernel<<<g, dim3(32, 8)>>>(x);
    }
    // 1) Q,K projections (fp32)
    {
        dim3 g(NPIX / 256, BATCH);
        qk_kernel<<<g, 256, 2 * CRD * CCH * sizeof(float)>>>(x, Wq, bq, Wk, bk);
    }
    // 2) V = bf16(Wv @ x + bv)   — HMMA
    {
        dim3 g(NPIX / 128, CCH / 128, BATCH);
        proj_mma_kernel<<<g, 256>>>((const __nv_bfloat16*)pWvh,
                                    (const __nv_bfloat16*)pxTh,
                                    (__nv_bfloat16*)pVh, nullptr,
                                    bv, nullptr, nullptr, CCH);
    }
    // 3) P = bf16(exp(Q @ K)), partial row sums
    {
        dim3 g(NPIX / 64, NPIX / 64, BATCH);
        scores_kernel<<<g, 256>>>();
    }
    // 4) fold partial sums
    reduce_sums_kernel<<<(BATCH * NPIX) / 8, 256>>>();
    // 5) O^T = ((V @ P^T)/sums)^T — HMMA
    {
        dim3 g(NPIX / 128, CCH / 128, BATCH);
        attn_mma_kernel<<<g, 256, 4 * ATT_STAGE * sizeof(__nv_bfloat16)>>>();
    }
    // 6) y = gamma * (Wo @ O + bo) + x — HMMA
    {
        dim3 g(NPIX / 128, CCH / 128, BATCH);
        proj_mma_kernel<<<g, 256>>>((const __nv_bfloat16*)pWoh,
                                    (const __nv_bfloat16*)pOTh,
                                    nullptr, out,
                                    bo, x, gamma, CCH);
    }
}